// round 5
// baseline (speedup 1.0000x reference)
#include <cuda_runtime.h>
#include <cuda_bf16.h>
#include <cstdint>

// ---------------------------------------------------------------------------
// GE2E loss, N_SPK=1024, N_UTT=32, D=128.
// bf16 HMMA GEMM of ehat[32768x128] x chat^T[128x1024]; w*log2e folded into
// ehat, b*log2e into accum init -> accums are log2(exp(logit)). Fused ex2
// row-sum; own-column fixed once at the end via ecorr = exp(ol) - exp(l_full).
// ---------------------------------------------------------------------------

#define NS 1024
#define NU 32
#define DD 128
#define NROWS (NS * NU)          // 32768
#define EPS 1e-8f
#define L2E 1.4426950408889634f

__device__ __align__(16) __nv_bfloat16 g_ehatb[NROWS * DD];   // 8 MB (pre-scaled w*log2e)
__device__ __align__(16) __nv_bfloat16 g_chatb[NS * DD];      // 256 KB
__device__ __align__(16) float2 g_own[NROWS];                 // (ol, ecorr)
__device__ __align__(16) float g_partial[NROWS / 64];         // 512

// ---------------- helpers ---------------------------------------------------
__device__ __forceinline__ uint32_t smem_u32(const void* p) {
    uint32_t a;
    asm("{ .reg .u64 t; cvta.to.shared.u64 t, %1; cvt.u32.u64 %0, t; }"
        : "=r"(a) : "l"(p));
    return a;
}
#define CP_ASYNC16(dst_u32, src_ptr) \
    asm volatile("cp.async.ca.shared.global [%0], [%1], 16;" :: "r"(dst_u32), "l"(src_ptr))
#define CP_COMMIT() asm volatile("cp.async.commit_group;")
#define CP_WAIT(n)  asm volatile("cp.async.wait_group %0;" :: "n"(n))

__device__ __forceinline__ void ldsm_x4(uint32_t addr, uint32_t& r0, uint32_t& r1,
                                        uint32_t& r2, uint32_t& r3) {
    asm volatile("ldmatrix.sync.aligned.m8n8.x4.shared.b16 {%0,%1,%2,%3}, [%4];"
                 : "=r"(r0), "=r"(r1), "=r"(r2), "=r"(r3) : "r"(addr));
}
__device__ __forceinline__ void mma16816(float* d, const uint32_t* a,
                                         uint32_t b0, uint32_t b1) {
    asm volatile(
        "mma.sync.aligned.m16n8k16.row.col.f32.bf16.bf16.f32 "
        "{%0,%1,%2,%3}, {%4,%5,%6,%7}, {%8,%9}, {%0,%1,%2,%3};"
        : "+f"(d[0]), "+f"(d[1]), "+f"(d[2]), "+f"(d[3])
        : "r"(a[0]), "r"(a[1]), "r"(a[2]), "r"(a[3]), "r"(b0), "r"(b1));
}

// stage a 64x128 bf16 tile (row-major 256B rows, contiguous 16KB) into smem
// with XOR-16B swizzle. 1024 16B chunks, 128 threads x 8.
__device__ __forceinline__ void stage_tile64(uint32_t sdst, const char* src, int tid) {
#pragma unroll
    for (int i = 0; i < 8; i++) {
        uint32_t q = (uint32_t)tid + i * 128u;       // 0..1023
        uint32_t r = q >> 4, c = q & 15u;
        uint32_t sw = r * 256u + ((c ^ (r & 7u)) << 4);
        CP_ASYNC16(sdst + sw, src + (size_t)q * 16);
    }
}

// ===========================================================================
// Kernel 1: prep (vectorized). block = 1 speaker, 128 threads.
// thread (wq,lane): rows m = wq + 4i (i<8), float4 at cols 4*lane.
// ===========================================================================
__global__ void __launch_bounds__(128) k_prep(const float* __restrict__ emb,
                                              const float* __restrict__ wp,
                                              const float* __restrict__ bp) {
    __shared__ float4 sred[4][32];

    const int n = blockIdx.x, t = threadIdx.x;
    const int wq = t >> 5, lane = t & 31;
    const float4* base = (const float4*)(emb + (size_t)n * NU * DD);

    float4 e4[8];
    float4 s4 = make_float4(0.f, 0.f, 0.f, 0.f);
#pragma unroll
    for (int i = 0; i < 8; i++) {
        e4[i] = base[(wq + 4 * i) * 32 + lane];
        s4.x += e4[i].x; s4.y += e4[i].y; s4.z += e4[i].z; s4.w += e4[i].w;
    }
    sred[wq][lane] = s4;
    __syncthreads();
    float4 S0 = sred[0][lane], S1 = sred[1][lane], S2_ = sred[2][lane], S3 = sred[3][lane];
    float4 S4;
    S4.x = S0.x + S1.x + S2_.x + S3.x;
    S4.y = S0.y + S1.y + S2_.y + S3.y;
    S4.z = S0.z + S1.z + S2_.z + S3.z;
    S4.w = S0.w + S1.w + S2_.w + S3.w;

    float s2 = S4.x * S4.x + S4.y * S4.y + S4.z * S4.z + S4.w * S4.w;
#pragma unroll
    for (int o = 16; o > 0; o >>= 1) s2 += __shfl_xor_sync(0xffffffffu, s2, o);
    const float S2 = s2;                   // same in every thread
    const float w = *wp, b = *bp;
    const float wl2e = w * L2E;
    const float cn = fmaxf(sqrtf(S2) * (1.f / NU), EPS);

    if (wq == 0) {                          // chat row (bf16, 8B per lane)
        float inv = (1.f / NU) / cn;
        __nv_bfloat162* dst = (__nv_bfloat162*)(g_chatb + n * DD + lane * 4);
        dst[0] = __nv_bfloat162(__float2bfloat16(S4.x * inv), __float2bfloat16(S4.y * inv));
        dst[1] = __nv_bfloat162(__float2bfloat16(S4.z * inv), __float2bfloat16(S4.w * inv));
    }

#pragma unroll
    for (int i = 0; i < 8; i++) {
        int m = wq + 4 * i;
        float dot = e4[i].x * S4.x + e4[i].y * S4.y + e4[i].z * S4.z + e4[i].w * S4.w;
        float e2  = e4[i].x * e4[i].x + e4[i].y * e4[i].y + e4[i].z * e4[i].z + e4[i].w * e4[i].w;
#pragma unroll
        for (int o = 16; o > 0; o >>= 1) {
            dot += __shfl_xor_sync(0xffffffffu, dot, o);
            e2  += __shfl_xor_sync(0xffffffffu, e2, o);
        }
        float en = fmaxf(sqrtf(e2), EPS);
        if (lane == 0) {
            float d2 = fmaxf(S2 - 2.f * dot + e2, 0.f);
            float cen = fmaxf(sqrtf(d2) * (1.f / (NU - 1)), EPS);
            float sim_ex = ((dot - e2) * (1.f / (NU - 1))) / (en * cen);
            float sim_fl = (dot * (1.f / NU)) / (en * cn);
            float ol = w * sim_ex + b;
            float lf = w * sim_fl + b;
            g_own[n * NU + m] = make_float2(ol, __expf(ol) - __expf(lf));
        }
        float sc = wl2e / en;               // broadcast of en via full-warp redundant compute
        __nv_bfloat162* dst = (__nv_bfloat162*)(g_ehatb + ((size_t)n * NU + m) * DD + lane * 4);
        dst[0] = __nv_bfloat162(__float2bfloat16(e4[i].x * sc), __float2bfloat16(e4[i].y * sc));
        dst[1] = __nv_bfloat162(__float2bfloat16(e4[i].z * sc), __float2bfloat16(e4[i].w * sc));
    }
}

// ===========================================================================
// Kernel 2: HMMA GEMM 64 rows/CTA x 1024 cols, fused ex2 row-sum + loss.
// 128 thr = 4 warps (2m x 2n), warp tile 32x32; 16 chunks of 64 cols,
// double-buffered cp.async. occ 4.
// ===========================================================================
#define SMEM_GEMM (1024 + 3 * 16384)

__global__ void __launch_bounds__(128, 4) k_gemm(const float* __restrict__ bp) {
    extern __shared__ char smc[];
    __shared__ float rowsum[64][2];
    __shared__ float redp[4];

    uint32_t sbase = (smem_u32(smc) + 1023u) & ~1023u;
    const uint32_t sA = sbase, sB0 = sbase + 16384u, sB1 = sB0 + 16384u;

    const int tid = threadIdx.x, wq = tid >> 5, lane = tid & 31;
    const int wm = wq >> 1, wn = wq & 1;
    const int rb = blockIdx.x * 64;

    stage_tile64(sA, (const char*)g_ehatb + (size_t)rb * 256, tid);
    stage_tile64(sB0, (const char*)g_chatb, tid);
    CP_COMMIT();
    stage_tile64(sB1, (const char*)g_chatb + 16384, tid);
    CP_COMMIT();

    const float bl2e = (*bp) * L2E;

    const uint32_t hxA = (uint32_t)(lane >> 4);
    const uint32_t rA = (uint32_t)(wm * 32 + (lane & 15));
    const uint32_t rxA = rA & 7u;
    const uint32_t baseA0 = sA + rA * 256u;
    const uint32_t baseA1 = baseA0 + 16u * 256u;
    uint32_t offB[2];
#pragma unroll
    for (int p = 0; p < 2; p++) {
        uint32_t nB = (uint32_t)(wn * 32 + p * 16 + (lane & 7) + ((lane >> 4) << 3));
        offB[p] = nB * 256u;
    }
    const uint32_t kxB = (uint32_t)((lane >> 3) & 1);
    const uint32_t rxB = (uint32_t)(lane & 7);

    float racc[4] = {0.f, 0.f, 0.f, 0.f};

    for (int ci = 0; ci < 16; ci++) {
        if (ci < 15) { CP_WAIT(1); } else { CP_WAIT(0); }
        __syncthreads();
        const uint32_t sB = (ci & 1) ? sB1 : sB0;

        float d[2][4][4];
#pragma unroll
        for (int mt = 0; mt < 2; mt++)
#pragma unroll
            for (int nt = 0; nt < 4; nt++)
#pragma unroll
                for (int e = 0; e < 4; e++) d[mt][nt][e] = bl2e;

#pragma unroll
        for (int k = 0; k < 8; k++) {
            uint32_t a0[4], a1[4], bfr[8];
            uint32_t ca = (((uint32_t)(2 * k) + hxA) ^ rxA) << 4;
            ldsm_x4(baseA0 + ca, a0[0], a0[1], a0[2], a0[3]);
            ldsm_x4(baseA1 + ca, a1[0], a1[1], a1[2], a1[3]);
            uint32_t cb = (((uint32_t)(2 * k) + kxB) ^ rxB) << 4;
#pragma unroll
            for (int p = 0; p < 2; p++)
                ldsm_x4(sB + offB[p] + cb,
                        bfr[4 * p], bfr[4 * p + 1], bfr[4 * p + 2], bfr[4 * p + 3]);
#pragma unroll
            for (int nt = 0; nt < 4; nt++) {
                mma16816(d[0][nt], a0, bfr[2 * nt], bfr[2 * nt + 1]);
                mma16816(d[1][nt], a1, bfr[2 * nt], bfr[2 * nt + 1]);
            }
        }

        __syncthreads();
        if (ci + 2 < 16) {
            stage_tile64((ci & 1) ? sB1 : sB0,
                         (const char*)g_chatb + (size_t)(ci + 2) * 16384, tid);
            CP_COMMIT();
        }

#pragma unroll
        for (int mt = 0; mt < 2; mt++)
#pragma unroll
            for (int nt = 0; nt < 4; nt++)
#pragma unroll
                for (int e = 0; e < 4; e++) {
                    float ev;
                    asm("ex2.approx.ftz.f32 %0, %1;" : "=f"(ev) : "f"(d[mt][nt][e]));
                    racc[mt * 2 + (e >> 1)] += ev;
                }
    }

#pragma unroll
    for (int j = 0; j < 4; j++) {
        racc[j] += __shfl_xor_sync(0xffffffffu, racc[j], 1);
        racc[j] += __shfl_xor_sync(0xffffffffu, racc[j], 2);
    }
    if ((lane & 3) == 0) {
        int g = lane >> 2;
#pragma unroll
        for (int j = 0; j < 4; j++) {
            int row = wm * 32 + (j >> 1) * 16 + (j & 1) * 8 + g;
            rowsum[row][wn] = racc[j];
        }
    }
    __syncthreads();

    float val = 0.f;
    if (tid < 64) {
        float Ssum = rowsum[tid][0] + rowsum[tid][1];
        float2 oc = g_own[rb + tid];
        val = __logf(Ssum + oc.y) - oc.x;
    }
#pragma unroll
    for (int o = 16; o > 0; o >>= 1) val += __shfl_xor_sync(0xffffffffu, val, o);
    if (lane == 0) redp[wq] = val;
    __syncthreads();
    if (tid == 0)
        g_partial[blockIdx.x] = redp[0] + redp[1];   // warps 2,3 contribute 0
}

// ===========================================================================
// Kernel 3: reduce 512 partials -> mean
// ===========================================================================
__global__ void __launch_bounds__(512) k_reduce(float* __restrict__ out) {
    const int t = threadIdx.x;
    float v = g_partial[t];
#pragma unroll
    for (int o = 16; o > 0; o >>= 1) v += __shfl_xor_sync(0xffffffffu, v, o);
    __shared__ float red[16];
    if ((t & 31) == 0) red[t >> 5] = v;
    __syncthreads();
    if (t == 0) {
        float x = 0.f;
#pragma unroll
        for (int i = 0; i < 16; i++) x += red[i];
        out[0] = x * (1.f / NROWS);
    }
}

// ===========================================================================
extern "C" void kernel_launch(void* const* d_in, const int* in_sizes, int n_in,
                              void* d_out, int out_size) {
    const float* emb = (const float*)d_in[0];
    const float* w   = (const float*)d_in[1];
    const float* b   = (const float*)d_in[2];

    cudaFuncSetAttribute(k_gemm, cudaFuncAttributeMaxDynamicSharedMemorySize,
                         SMEM_GEMM);

    k_prep<<<NS, 128>>>(emb, w, b);
    k_gemm<<<NROWS / 64, 128, SMEM_GEMM>>>(b);
    k_reduce<<<1, 512>>>((float*)d_out);
}